// round 14
// baseline (speedup 1.0000x reference)
#include <cuda_runtime.h>
#include <cuda_fp16.h>
#include <cstdint>

#define SEQ 256
#define B_  32
#define TILE 4096   // 64*64 floats

// LAYOUT L4 (verified): tile (b,t) at (t*32+b)*TILE; interior transposed:
// element (i,j) at offset j*64 + i.

__device__ float g_fv[32][64];
__device__ float g_bv[32][64];
__device__ float g_fo[32];
__device__ float g_bo[32];
__device__ float g_sc[32];
__device__ int   g_ct[32];
__device__ int   g_done;
__device__ float g_sink;

__device__ __forceinline__ void cp16(unsigned int dst, const float* src) {
    asm volatile("cp.async.cg.shared.global [%0], [%1], 16;\n" :: "r"(dst), "l"(src));
}
__device__ __forceinline__ void cp_commit() { asm volatile("cp.async.commit_group;\n" ::: "memory"); }
__device__ __forceinline__ void cp_wait2()  { asm volatile("cp.async.wait_group 2;\n" ::: "memory"); }

// fwd stage swizzle: 16B chunk cw (0..15) of row r stored at S(cw,r).
// Bijective per row; makes both the cp.async stores and the (o,sg) quad reads
// 8-lane-phase conflict-free.
#define SWZ(cw, r) (((cw) ^ (((cw) >> 3) * 6)) ^ ((r) & 1))

__device__ __forceinline__ int bf16_ok(unsigned h) {
    const float g = __uint_as_float(h << 16);
    return (h == 0u) || (g >= 1.f && g < 64.f && g == floorf(g));
}
__device__ __forceinline__ int decode_tgt(const unsigned* tu, int mode, int e) {
    int v;
    if      (mode == 0) v = (int)tu[2 * e];
    else if (mode == 1) v = (int)tu[e];
    else if (mode == 2) v = (int)((tu[e >> 1] >> ((e & 1) * 16)) & 0xFFFFu);
    else if (mode == 3) v = (int)((tu[e >> 2] >> ((e & 3) * 8)) & 0xFFu);
    else if (mode == 4) v = (int)__uint_as_float(tu[e]);
    else if (mode == 5) v = (int)__uint_as_float(((tu[e >> 1] >> ((e & 1) * 16)) & 0xFFFFu) << 16);
    else                v = (int)__hiloint2double(tu[2 * e + 1], tu[2 * e]);
    return v & 63;
}

__device__ __forceinline__ float4 exp4f(float4 e) {
    const float L2E = 1.4426950408889634f;
    __half2 ha = h2exp2(__floats2half2_rn(e.x * L2E, e.y * L2E));
    __half2 hb = h2exp2(__floats2half2_rn(e.z * L2E, e.w * L2E));
    const float2 fa = __half22float2(ha);
    const float2 fb = __half22float2(hb);
    return make_float4(fa.x, fa.y, fb.x, fb.y);
}

// -------------------------------------------------------------------------
// grid = 148: blocks 0..63 scan chains (b=blk>>1, dir=blk&1);
// blocks 64..147 L2-warming helpers. Block 0 finishes the loss.
// -------------------------------------------------------------------------
__global__ void __launch_bounds__(256) crf_fused(const float* __restrict__ emits,
                                                 const unsigned char* __restrict__ mask,
                                                 const unsigned* __restrict__ tu,
                                                 float* __restrict__ out)
{
    const int blk = blockIdx.x;
    const int tid = threadIdx.x;

    if (blk >= 64) {
        float acc = 0.f;
        for (int w = blk - 64; w < 8160; w += 84) {
            const int dd = w >> 6, r = w & 63;
            if (dd == 127 && r >= 32) continue;
            const int t = (r & 32) ? 255 - dd : 1 + dd;
            const int b = r & 31;
            const float4* src = (const float4*)(emits + (size_t)(t * B_ + b) * TILE);
            #pragma unroll
            for (int k = 0; k < 4; k++) {
                const float4 v = __ldcg(&src[k * 256 + tid]);
                acc += v.x + v.y + v.z + v.w;
            }
        }
        if (acc == 1.234567e-33f) g_sink = acc;
        return;
    }

    extern __shared__ float smem[];
    float* stage = smem;                    // 4 x 4096
    float* A0p   = smem + 16384;            // 84 (padded fwd / 64 used bwd)
    float* A1p   = A0p + 84;                // 84
    float* sMax  = A1p + 84;                // 8
    __shared__ unsigned char sM[256];
    __shared__ float sRed2[2];
    __shared__ float sv[8];
    __shared__ int   scnt[8];
    __shared__ double sAcc[8];
    __shared__ int   sCt2[8];

    const int b = blk >> 1, dir = blk & 1;
    const unsigned int stage_u32 = (unsigned int)__cvta_generic_to_shared(stage);

    sM[tid] = mask[b * SEQ + tid];
    const int nsteps = dir ? 128 : 127;

    // per-thread cp.async destination offsets (dir-specific swizzle)
    unsigned int cp_d[4];
    const float4* cp_s[4];
    #pragma unroll
    for (int k = 0; k < 4; k++) {
        const int m = k * 256 + tid;
        const int row = m >> 4, c = m & 15;
        const int sw = dir ? (c ^ ((row >> 2) & 7)) : SWZ(c, row);
        cp_d[k] = (unsigned int)((row * 64 + sw * 4) * 4);
        cp_s[k] = (const float4*)nullptr;   // set per-stage below
    }

    // prologue: issue stages 0..2
    #pragma unroll
    for (int s = 0; s < 3; s++) {
        const int t = dir ? 255 - s : 1 + s;
        const float* src = emits + (size_t)(t * B_ + b) * TILE;
        const unsigned int stg = stage_u32 + (unsigned int)s * 16384u;
        #pragma unroll
        for (int k = 0; k < 4; k++) cp16(stg + cp_d[k], src + (k * 256 + tid) * 4);
        cp_commit();
    }

    // init alpha (buffer 0)
    float m0 = 0.f;
    if (dir == 0) {
        float e0 = (tid < 64) ? emits[(size_t)b * TILE + tid * 64] : -1e30f;
        if (tid < 64) {
            float v = e0;
            #pragma unroll
            for (int o = 16; o; o >>= 1) v = fmaxf(v, __shfl_xor_sync(~0u, v, o));
            if ((tid & 31) == 0) sRed2[tid >> 5] = v;
        }
        __syncthreads();
        m0 = fmaxf(sRed2[0], sRed2[1]);
        if (tid < 64) A0p[tid + (tid >> 4) * 4] = __expf(e0 - m0);   // padded
    } else {
        if (tid < 64) A0p[tid] = 1.f;                                // flat
    }

    cp_wait2();
    __syncthreads();   // stage0 visible to all; alpha0 visible

    int K = 0;

    if (dir == 0) {
        // ================= FORWARD: T=4 mapping =================
        const int o = tid >> 2, sg = tid & 3;
        unsigned int rd[4];
        #pragma unroll
        for (int q = 0; q < 4; q++) rd[q] = (unsigned int)(o * 64 + SWZ(4 * sg + q, o) * 4);

        float4 pc[4], pn[4];
        #pragma unroll
        for (int q = 0; q < 4; q++) pc[q] = exp4f(*(const float4*)&stage[rd[q]]);

        for (int s = 0; s < nsteps; s++) {
            // issue stage s+3, retire stage s+1
            {
                const int sp = s + 3;
                if (sp < nsteps) {
                    const int t = 1 + sp;
                    const float* src = emits + (size_t)(t * B_ + b) * TILE;
                    const unsigned int stg = stage_u32 + (unsigned int)(sp & 3) * 16384u;
                    #pragma unroll
                    for (int k = 0; k < 4; k++) cp16(stg + cp_d[k], src + (k * 256 + tid) * 4);
                }
                cp_commit();
                cp_wait2();
            }
            __syncthreads();   // orders: prev alpha writes + stage s+1 cp landing

            // prefetch & exp next tile (independent of alpha)
            if (s + 1 < nsteps) {
                const float* stn = stage + ((s + 1) & 3) * 4096;
                #pragma unroll
                for (int q = 0; q < 4; q++) pn[q] = exp4f(*(const float4*)&stn[rd[q]]);
            }

            const float* Ac = (s & 1) ? A1p : A0p;
            float*       An = (s & 1) ? A0p : A1p;

            const float4 a0 = *(const float4*)&Ac[20 * sg + 0];
            const float4 a1 = *(const float4*)&Ac[20 * sg + 4];
            const float4 a2 = *(const float4*)&Ac[20 * sg + 8];
            const float4 a3 = *(const float4*)&Ac[20 * sg + 12];
            const float aold = Ac[o + (o >> 4) * 4];

            float y0 = a0.x * pc[0].x + a0.y * pc[0].y + a0.z * pc[0].z + a0.w * pc[0].w;
            float y1 = a1.x * pc[1].x + a1.y * pc[1].y + a1.z * pc[1].z + a1.w * pc[1].w;
            float y2 = a2.x * pc[2].x + a2.y * pc[2].y + a2.z * pc[2].z + a2.w * pc[2].w;
            float y3 = a3.x * pc[3].x + a3.y * pc[3].y + a3.z * pc[3].z + a3.w * pc[3].w;
            float y = (y0 + y1) + (y2 + y3);
            y += __shfl_xor_sync(~0u, y, 1);
            y += __shfl_xor_sync(~0u, y, 2);

            const bool msk = sM[1 + s] != 0;
            if ((s & 7) == 7) {
                float m = y;
                m = fmaxf(m, __shfl_xor_sync(~0u, m, 4));
                m = fmaxf(m, __shfl_xor_sync(~0u, m, 8));
                m = fmaxf(m, __shfl_xor_sync(~0u, m, 16));
                if ((tid & 31) == 0) sMax[tid >> 5] = m;
                __syncthreads();
                const float4 x0 = *(const float4*)&sMax[0];
                const float4 x1 = *(const float4*)&sMax[4];
                const float gm = fmaxf(fmaxf(fmaxf(x0.x, x0.y), fmaxf(x0.z, x0.w)),
                                       fmaxf(fmaxf(x1.x, x1.y), fmaxf(x1.z, x1.w)));
                if (msk) {
                    const int kx = ((__float_as_int(gm) >> 23) & 0xFF) - 127;
                    y *= __int_as_float((127 - kx) << 23);
                    K += kx;
                }
            }
            if (sg == 0) An[o + (o >> 4) * 4] = msk ? y : aold;

            #pragma unroll
            for (int q = 0; q < 4; q++) pc[q] = pn[q];
        }

        __syncthreads();
        const float* Af = (nsteps & 1) ? A1p : A0p;
        if (tid < 64) g_fv[b][tid] = Af[tid + (tid >> 4) * 4];
        if (tid == 0) g_fo[b] = (float)K * 0.6931471805599453f + m0;
    } else {
        // ================= BACKWARD: T=16 mapping (R12) =================
        const int sidx = tid & 15, oidx = tid >> 4;
        unsigned int rd[4];
        #pragma unroll
        for (int r = 0; r < 4; r++)
            rd[r] = (unsigned int)((sidx * 4 + r) * 64 + ((oidx ^ (sidx & 7)) << 2));

        float4 pc[4], pn[4];
        #pragma unroll
        for (int r = 0; r < 4; r++) pc[r] = exp4f(*(const float4*)&stage[rd[r]]);

        for (int s = 0; s < nsteps; s++) {
            {
                const int sp = s + 3;
                if (sp < nsteps) {
                    const int t = 255 - sp;
                    const float* src = emits + (size_t)(t * B_ + b) * TILE;
                    const unsigned int stg = stage_u32 + (unsigned int)(sp & 3) * 16384u;
                    #pragma unroll
                    for (int k = 0; k < 4; k++) cp16(stg + cp_d[k], src + (k * 256 + tid) * 4);
                }
                cp_commit();
                cp_wait2();
            }
            __syncthreads();

            if (s + 1 < nsteps) {
                const float* stn = stage + ((s + 1) & 3) * 4096;
                #pragma unroll
                for (int r = 0; r < 4; r++) pn[r] = exp4f(*(const float4*)&stn[rd[r]]);
            }

            const float* Ac = (s & 1) ? A1p : A0p;
            float*       An = (s & 1) ? A0p : A1p;

            const float4 A4 = *(const float4*)&Ac[sidx * 4];
            const float4 aold4 = *(const float4*)&Ac[oidx * 4];

            float4 acc;
            acc.x = A4.x * pc[0].x + A4.y * pc[1].x + A4.z * pc[2].x + A4.w * pc[3].x;
            acc.y = A4.x * pc[0].y + A4.y * pc[1].y + A4.z * pc[2].y + A4.w * pc[3].y;
            acc.z = A4.x * pc[0].z + A4.y * pc[1].z + A4.z * pc[2].z + A4.w * pc[3].z;
            acc.w = A4.x * pc[0].w + A4.y * pc[1].w + A4.z * pc[2].w + A4.w * pc[3].w;
            #pragma unroll
            for (int o2 = 1; o2 <= 8; o2 <<= 1) {
                acc.x += __shfl_xor_sync(~0u, acc.x, o2);
                acc.y += __shfl_xor_sync(~0u, acc.y, o2);
                acc.z += __shfl_xor_sync(~0u, acc.z, o2);
                acc.w += __shfl_xor_sync(~0u, acc.w, o2);
            }

            const bool msk = sM[255 - s] != 0;
            if ((s & 7) == 7) {
                float m = fmaxf(fmaxf(acc.x, acc.y), fmaxf(acc.z, acc.w));
                m = fmaxf(m, __shfl_xor_sync(~0u, m, 16));
                if ((tid & 31) == 0) sMax[tid >> 5] = m;
                __syncthreads();
                const float4 x0 = *(const float4*)&sMax[0];
                const float4 x1 = *(const float4*)&sMax[4];
                const float gm = fmaxf(fmaxf(fmaxf(x0.x, x0.y), fmaxf(x0.z, x0.w)),
                                       fmaxf(fmaxf(x1.x, x1.y), fmaxf(x1.z, x1.w)));
                if (msk) {
                    const int kx = ((__float_as_int(gm) >> 23) & 0xFF) - 127;
                    const float sc2 = __int_as_float((127 - kx) << 23);
                    K += kx;
                    acc.x *= sc2; acc.y *= sc2; acc.z *= sc2; acc.w *= sc2;
                }
            }
            if (sidx == 0) {
                float4 wv;
                wv.x = msk ? acc.x : aold4.x;
                wv.y = msk ? acc.y : aold4.y;
                wv.z = msk ? acc.z : aold4.z;
                wv.w = msk ? acc.w : aold4.w;
                *(float4*)&An[oidx * 4] = wv;
            }
            #pragma unroll
            for (int r = 0; r < 4; r++) pc[r] = pn[r];
        }

        __syncthreads();
        const float* Af = (nsteps & 1) ? A1p : A0p;
        if (tid < 64) g_bv[b][tid] = Af[tid];
        if (tid == 0) g_bo[b] = (float)K * 0.6931471805599453f;
    }

    // ---- dir==0 epilogue: path score ----
    if (dir == 0) {
        const unsigned w  = tu[tid];
        const unsigned h0 = w & 0xFFFFu, h1 = w >> 16;
        const float    f  = __uint_as_float(w);
        int okA = (tid & 1) ? (w == 0u) : (w < 64u);
        int okB = (w < 64u);
        int okI = (h0 < 64u) && (h1 < 64u);
        int okE = ((w & 0xC0C0C0C0u) == 0u);
        int okC = (w == 0u) || (f >= 1.f && f < 64.f && f == floorf(f));
        int okF = bf16_ok(h0) && bf16_ok(h1);
        okA = __syncthreads_and(okA);
        okB = __syncthreads_and(okB);
        okI = __syncthreads_and(okI);
        okE = __syncthreads_and(okE);
        okC = __syncthreads_and(okC);
        okF = __syncthreads_and(okF);
        const int mode = okA ? 0 : okB ? 1 : okI ? 2 : okE ? 3 : okC ? 4 : okF ? 5 : 6;

        const int row = b * (SEQ + 1);
        const int i0 = decode_tgt(tu, mode, row + tid);
        const int i1 = decode_tgt(tu, mode, row + tid + 1);

        float v = 0.f; int c = 0;
        if (sM[tid]) {
            v = emits[(size_t)(tid * B_ + b) * TILE + i1 * 64 + i0];
            c = 1;
        }
        #pragma unroll
        for (int o = 16; o; o >>= 1) {
            v += __shfl_xor_sync(~0u, v, o);
            c += __shfl_xor_sync(~0u, c, o);
        }
        if ((tid & 31) == 0) { sv[tid >> 5] = v; scnt[tid >> 5] = c; }
        __syncthreads();
        if (tid == 0) {
            float tv = 0.f; int tc = 0;
            #pragma unroll
            for (int k = 0; k < 8; k++) { tv += sv[k]; tc += scnt[k]; }
            g_sc[b] = tv;
            g_ct[b] = tc;
        }
    }

    __threadfence();
    __syncthreads();
    if (tid == 0) atomicAdd(&g_done, 1);

    if (blk == 0) {
        if (tid == 0) {
            while (atomicAdd(&g_done, 0) < 64) __nanosleep(64);
            __threadfence();
        }
        __syncthreads();
        const int w = tid >> 5, l = tid & 31;
        double accd = 0.0; int ctd = 0;
        for (int bb = w; bb < 32; bb += 8) {
            float part = g_fv[bb][l] * g_bv[bb][l] + g_fv[bb][l + 32] * g_bv[bb][l + 32];
            #pragma unroll
            for (int o = 16; o; o >>= 1) part += __shfl_xor_sync(~0u, part, o);
            if (l == 0) {
                accd += (double)(logf(part) + g_fo[bb] + g_bo[bb]) - (double)g_sc[bb];
                ctd  += g_ct[bb];
            }
        }
        if (l == 0) { sAcc[w] = accd; sCt2[w] = ctd; }
        __syncthreads();
        if (tid == 0) {
            double s = 0.0; int c = 0;
            #pragma unroll
            for (int k = 0; k < 8; k++) { s += sAcc[k]; c += sCt2[k]; }
            out[0] = (float)(s / (double)c);
            __threadfence();
            g_done = 0;
        }
    }
}

extern "C" void kernel_launch(void* const* d_in, const int* in_sizes, int n_in,
                              void* d_out, int out_size)
{
    int ie = 0;
    for (int k = 1; k < n_in; k++) if (in_sizes[k] > in_sizes[ie]) ie = k;
    int im = -1, it = -1;
    for (int k = 0; k < n_in; k++) {
        if (k == ie) continue;
        if (in_sizes[k] == 8192 && im < 0) im = k; else it = k;
    }
    if (im < 0) { im = 2; }
    if (it < 0) { it = (im == 1) ? 2 : 1; }

    const float*         emits = (const float*)d_in[ie];
    const unsigned*      tg    = (const unsigned*)d_in[it];
    const unsigned char* mask  = (const unsigned char*)d_in[im];

    const int smem_bytes = (16384 + 84 + 84 + 8) * 4;   // 66240
    cudaFuncSetAttribute(crf_fused, cudaFuncAttributeMaxDynamicSharedMemorySize, smem_bytes);

    crf_fused<<<148, 256, smem_bytes>>>(emits, mask, tg, (float*)d_out);
}

// round 15
// speedup vs baseline: 1.0453x; 1.0453x over previous
#include <cuda_runtime.h>
#include <cstdint>

#define SEQ 256
#define B_  32
#define TILE 4096   // 64*64 floats
#define NSTG 8      // cp.async ring depth (16KB per stage)

// LAYOUT L4 (verified): tile (b,t) at (t*32+b)*TILE; interior transposed:
// element (i,j) at offset j*64 + i.

__device__ float g_fv[32][64];
__device__ float g_bv[32][64];
__device__ float g_fo[32];
__device__ float g_bo[32];
__device__ float g_sc[32];
__device__ int   g_ct[32];
__device__ int   g_done;

__device__ __forceinline__ void cp16(unsigned int dst, const float* src) {
    asm volatile("cp.async.cg.shared.global [%0], [%1], 16;\n" :: "r"(dst), "l"(src));
}
__device__ __forceinline__ void cp_commit() { asm volatile("cp.async.commit_group;\n" ::: "memory"); }
__device__ __forceinline__ void cp_wait6()  { asm volatile("cp.async.wait_group 6;\n" ::: "memory"); }

__device__ __forceinline__ int bf16_ok(unsigned h) {
    const float g = __uint_as_float(h << 16);
    return (h == 0u) || (g >= 1.f && g < 64.f && g == floorf(g));
}
__device__ __forceinline__ int decode_tgt(const unsigned* tu, int mode, int e) {
    int v;
    if      (mode == 0) v = (int)tu[2 * e];
    else if (mode == 1) v = (int)tu[e];
    else if (mode == 2) v = (int)((tu[e >> 1] >> ((e & 1) * 16)) & 0xFFFFu);
    else if (mode == 3) v = (int)((tu[e >> 2] >> ((e & 3) * 8)) & 0xFFu);
    else if (mode == 4) v = (int)__uint_as_float(tu[e]);
    else if (mode == 5) v = (int)__uint_as_float(((tu[e >> 1] >> ((e & 1) * 16)) & 0xFFFFu) << 16);
    else                v = (int)__hiloint2double(tu[2 * e + 1], tu[2 * e]);
    return v & 63;
}

// -------------------------------------------------------------------------
// grid = 64: block blk -> batch b = blk>>1, dir = blk&1. R12 body with an
// 8-stage cp.async ring (96KB in flight). Block 0 finishes the loss.
// -------------------------------------------------------------------------
__global__ void __launch_bounds__(256) crf_fused(const float* __restrict__ emits,
                                                 const unsigned char* __restrict__ mask,
                                                 const unsigned* __restrict__ tu,
                                                 float* __restrict__ out)
{
    extern __shared__ float smem[];
    float* stage = smem;                        // NSTG x 4096 floats
    float* sA    = smem + NSTG * 4096;          // 64
    float* sMax  = sA + 64;                     // 8
    __shared__ unsigned char sM[256];
    __shared__ float sRed2[2];
    __shared__ float sv[8];
    __shared__ int   scnt[8];
    __shared__ double sAcc[8];
    __shared__ int   sCt2[8];

    const int blk = blockIdx.x;
    const int tid = threadIdx.x;
    const int b = blk >> 1, dir = blk & 1;
    const int sidx = tid & 15;
    const int oidx = tid >> 4;
    const int rb   = dir ? sidx : oidx;     // row-block (rows 4rb..+3)
    const int cc   = dir ? oidx : sidx;     // column chunk (cols 4cc..+3)
    const int rdoff = ((cc ^ (rb & 7)) << 2);

    const unsigned int stage_u32 = (unsigned int)__cvta_generic_to_shared(stage);

    int cp_m[4];
    unsigned int cp_d[4];
    #pragma unroll
    for (int k = 0; k < 4; k++) {
        const int m = k * 256 + tid;
        const int row = m >> 4, c = m & 15;
        cp_m[k] = m;
        cp_d[k] = (unsigned int)((row * 64 + ((c ^ ((row >> 2) & 7)) << 2)) * 4);
    }

    sM[tid] = mask[b * SEQ + tid];

    const int nsteps = dir ? 128 : 127;

    // prologue: 7 stages in flight
    #pragma unroll
    for (int s = 0; s < NSTG - 1; s++) {
        const int t = dir ? 255 - s : 1 + s;
        const float* src = emits + (size_t)(t * B_ + b) * TILE;
        const unsigned int stg = stage_u32 + (unsigned int)(s & (NSTG - 1)) * 16384u;
        #pragma unroll
        for (int k = 0; k < 4; k++) cp16(stg + cp_d[k], src + cp_m[k] * 4);
        cp_commit();
    }

    // init state
    float m0 = 0.f;
    if (dir == 0) {
        float e0 = (tid < 64) ? emits[(size_t)b * TILE + tid * 64] : -1e30f;
        if (tid < 64) {
            float v = e0;
            #pragma unroll
            for (int o = 16; o; o >>= 1) v = fmaxf(v, __shfl_xor_sync(~0u, v, o));
            if ((tid & 31) == 0) sRed2[tid >> 5] = v;
        }
        __syncthreads();
        m0 = fmaxf(sRed2[0], sRed2[1]);
        if (tid < 64) sA[tid] = __expf(e0 - m0);
    } else {
        if (tid < 64) sA[tid] = 1.f;
    }

    int K = 0;
    for (int s = 0; s < nsteps; s++) {
        cp_wait6();
        __syncthreads();           // stage s ready; sA from prev step visible

        // issue stage s+7
        {
            const int sp = s + NSTG - 1;
            if (sp < nsteps) {
                const int t = dir ? 255 - sp : 1 + sp;
                const float* src = emits + (size_t)(t * B_ + b) * TILE;
                const unsigned int stg = stage_u32 + (unsigned int)(sp & (NSTG - 1)) * 16384u;
                #pragma unroll
                for (int k = 0; k < 4; k++) cp16(stg + cp_d[k], src + cp_m[k] * 4);
            }
            cp_commit();
        }

        const float* st = stage + (s & (NSTG - 1)) * 4096;
        const float4 A4 = *(const float4*)&sA[sidx * 4];

        const float4 e0 = *(const float4*)&st[(rb * 4 + 0) * 64 + rdoff];
        const float4 e1 = *(const float4*)&st[(rb * 4 + 1) * 64 + rdoff];
        const float4 e2 = *(const float4*)&st[(rb * 4 + 2) * 64 + rdoff];
        const float4 e3 = *(const float4*)&st[(rb * 4 + 3) * 64 + rdoff];
        const float4 p0 = make_float4(__expf(e0.x), __expf(e0.y), __expf(e0.z), __expf(e0.w));
        const float4 p1 = make_float4(__expf(e1.x), __expf(e1.y), __expf(e1.z), __expf(e1.w));
        const float4 p2 = make_float4(__expf(e2.x), __expf(e2.y), __expf(e2.z), __expf(e2.w));
        const float4 p3 = make_float4(__expf(e3.x), __expf(e3.y), __expf(e3.z), __expf(e3.w));

        float4 acc;
        if (dir == 0) {
            acc.x = A4.x * p0.x + A4.y * p0.y + A4.z * p0.z + A4.w * p0.w;
            acc.y = A4.x * p1.x + A4.y * p1.y + A4.z * p1.z + A4.w * p1.w;
            acc.z = A4.x * p2.x + A4.y * p2.y + A4.z * p2.z + A4.w * p2.w;
            acc.w = A4.x * p3.x + A4.y * p3.y + A4.z * p3.z + A4.w * p3.w;
        } else {
            acc.x = A4.x * p0.x + A4.y * p1.x + A4.z * p2.x + A4.w * p3.x;
            acc.y = A4.x * p0.y + A4.y * p1.y + A4.z * p2.y + A4.w * p3.y;
            acc.z = A4.x * p0.z + A4.y * p1.z + A4.z * p2.z + A4.w * p3.z;
            acc.w = A4.x * p0.w + A4.y * p1.w + A4.z * p2.w + A4.w * p3.w;
        }

        #pragma unroll
        for (int o = 1; o <= 8; o <<= 1) {
            acc.x += __shfl_xor_sync(~0u, acc.x, o);
            acc.y += __shfl_xor_sync(~0u, acc.y, o);
            acc.z += __shfl_xor_sync(~0u, acc.z, o);
            acc.w += __shfl_xor_sync(~0u, acc.w, o);
        }

        const int t = dir ? 255 - s : 1 + s;
        const bool msk = sM[t] != 0;

        if ((s & 3) == 3) {   // renorm step (uniform branch)
            float m = fmaxf(fmaxf(acc.x, acc.y), fmaxf(acc.z, acc.w));
            m = fmaxf(m, __shfl_xor_sync(~0u, m, 16));
            if ((tid & 31) == 0) sMax[tid >> 5] = m;
            __syncthreads();
            const float4 x0 = *(const float4*)&sMax[0];
            const float4 x1 = *(const float4*)&sMax[4];
            const float gm = fmaxf(fmaxf(fmaxf(x0.x, x0.y), fmaxf(x0.z, x0.w)),
                                   fmaxf(fmaxf(x1.x, x1.y), fmaxf(x1.z, x1.w)));
            if (msk) {
                const int kx = ((__float_as_int(gm) >> 23) & 0xFF) - 127;   // ilogb
                const float scale = __int_as_float((127 - kx) << 23);       // exact 2^-kx
                K += kx;
                acc.x *= scale; acc.y *= scale; acc.z *= scale; acc.w *= scale;
            }
        }

        if (msk && sidx == 0) *(float4*)&sA[oidx * 4] = acc;
    }

    __syncthreads();
    if (tid < 64) {
        if (dir == 0) g_fv[b][tid] = sA[tid];
        else          g_bv[b][tid] = sA[tid];
    }
    if (tid == 0) {
        const float off = (float)K * 0.6931471805599453f + (dir ? 0.f : m0);
        if (dir == 0) g_fo[b] = off; else g_bo[b] = off;
    }

    // ---- dir==0 epilogue: path score for batch b ----
    if (dir == 0) {
        const unsigned w  = tu[tid];
        const unsigned h0 = w & 0xFFFFu, h1 = w >> 16;
        const float    f  = __uint_as_float(w);
        int okA = (tid & 1) ? (w == 0u) : (w < 64u);
        int okB = (w < 64u);
        int okI = (h0 < 64u) && (h1 < 64u);
        int okE = ((w & 0xC0C0C0C0u) == 0u);
        int okC = (w == 0u) || (f >= 1.f && f < 64.f && f == floorf(f));
        int okF = bf16_ok(h0) && bf16_ok(h1);
        okA = __syncthreads_and(okA);
        okB = __syncthreads_and(okB);
        okI = __syncthreads_and(okI);
        okE = __syncthreads_and(okE);
        okC = __syncthreads_and(okC);
        okF = __syncthreads_and(okF);
        const int mode = okA ? 0 : okB ? 1 : okI ? 2 : okE ? 3 : okC ? 4 : okF ? 5 : 6;

        const int row = b * (SEQ + 1);
        const int i0 = decode_tgt(tu, mode, row + tid);
        const int i1 = decode_tgt(tu, mode, row + tid + 1);

        float v = 0.f; int c = 0;
        if (sM[tid]) {
            v = emits[(size_t)(tid * B_ + b) * TILE + i1 * 64 + i0];
            c = 1;
        }
        #pragma unroll
        for (int o = 16; o; o >>= 1) {
            v += __shfl_xor_sync(~0u, v, o);
            c += __shfl_xor_sync(~0u, c, o);
        }
        if ((tid & 31) == 0) { sv[tid >> 5] = v; scnt[tid >> 5] = c; }
        __syncthreads();
        if (tid == 0) {
            float tv = 0.f; int tc = 0;
            #pragma unroll
            for (int k = 0; k < 8; k++) { tv += sv[k]; tc += scnt[k]; }
            g_sc[b] = tv;
            g_ct[b] = tc;
        }
    }

    // ---- arrive; block 0 finishes the loss ----
    __threadfence();
    __syncthreads();
    if (tid == 0) atomicAdd(&g_done, 1);

    if (blk == 0) {
        if (tid == 0) {
            while (atomicAdd(&g_done, 0) < 64) __nanosleep(64);
            __threadfence();
        }
        __syncthreads();

        const int w = tid >> 5, l = tid & 31;
        double accd = 0.0; int ctd = 0;
        for (int bb = w; bb < 32; bb += 8) {
            float part = g_fv[bb][l] * g_bv[bb][l] + g_fv[bb][l + 32] * g_bv[bb][l + 32];
            #pragma unroll
            for (int o = 16; o; o >>= 1) part += __shfl_xor_sync(~0u, part, o);
            if (l == 0) {
                accd += (double)(logf(part) + g_fo[bb] + g_bo[bb]) - (double)g_sc[bb];
                ctd  += g_ct[bb];
            }
        }
        if (l == 0) { sAcc[w] = accd; sCt2[w] = ctd; }
        __syncthreads();
        if (tid == 0) {
            double s = 0.0; int c = 0;
            #pragma unroll
            for (int k = 0; k < 8; k++) { s += sAcc[k]; c += sCt2[k]; }
            out[0] = (float)(s / (double)c);
            __threadfence();
            g_done = 0;   // reset for next graph replay
        }
    }
}

extern "C" void kernel_launch(void* const* d_in, const int* in_sizes, int n_in,
                              void* d_out, int out_size)
{
    int ie = 0;
    for (int k = 1; k < n_in; k++) if (in_sizes[k] > in_sizes[ie]) ie = k;
    int im = -1, it = -1;
    for (int k = 0; k < n_in; k++) {
        if (k == ie) continue;
        if (in_sizes[k] == 8192 && im < 0) im = k; else it = k;
    }
    if (im < 0) { im = 2; }
    if (it < 0) { it = (im == 1) ? 2 : 1; }

    const float*         emits = (const float*)d_in[ie];
    const unsigned*      tg    = (const unsigned*)d_in[it];
    const unsigned char* mask  = (const unsigned char*)d_in[im];

    const int smem_bytes = NSTG * 4096 * 4 + (64 + 8) * 4;   // 131360
    cudaFuncSetAttribute(crf_fused, cudaFuncAttributeMaxDynamicSharedMemorySize, smem_bytes);

    crf_fused<<<64, 256, smem_bytes>>>(emits, mask, tg, (float*)d_out);
}